// round 5
// baseline (speedup 1.0000x reference)
#include <cuda_runtime.h>
#include <cuda_bf16.h>
#include <cstdint>

// CNOT permutation: out[lin(i)*batch + b] = x[i*batch + b]
// d==2, pow2 batch>=4 fast path at float4 granularity:
//   v' = v XOR (bit(v, sc+lb-2) << (st+lb-2)),  lb = log2(batch)
// where sc = n-1-control, st = n-1-target.
// Persistent grid-stride kernel: fixed grid (SMs * CTAs/SM), zero wave
// transitions. Loads default-cached, stores evict-first (never re-read).

#define VPT 4    // float4 vectors per loop iteration per thread
#define BLK 256
#define GRID 1184  // 148 SMs * 8 resident CTAs

__global__ __launch_bounds__(BLK) void cnot_kernel(
    const float4* __restrict__ x4, float4* __restrict__ out4,
    const int* __restrict__ p_control, const int* __restrict__ p_target,
    const int* __restrict__ p_d, const int* __restrict__ p_n,
    unsigned int nvec, unsigned int total)
{
    const int control = __ldg(p_control);
    const int target  = __ldg(p_target);
    const int d       = __ldg(p_d);
    const int n       = __ldg(p_n);

    bool fast = false;
    unsigned int shC = 0, shT = 0;
    if (d == 2 && n >= 1 && n < 32) {
        const unsigned int batch = total >> n;
        if ((batch << n) == total && batch >= 4u &&
            (batch & (batch - 1u)) == 0u) {
            const unsigned int lb = 31u - __clz(batch);
            shT = (unsigned int)(n - 1 - target) + lb - 2u;
            shC = (unsigned int)(n - 1 - control) + lb - 2u;
            fast = true;
        }
    }

    if (fast) {
        const unsigned int tileV   = (unsigned int)(BLK * VPT);      // vectors per tile
        const unsigned int strideV = tileV * gridDim.x;              // vectors per sweep
        unsigned int base = blockIdx.x * tileV + threadIdx.x;

        // full tiles
        for (; base + (VPT - 1) * BLK < nvec; base += strideV) {
            float4 a[VPT];
            unsigned int dst[VPT];
            #pragma unroll
            for (int k = 0; k < VPT; k++) {
                unsigned int v = base + (unsigned int)k * BLK;
                a[k]   = __ldg(&x4[v]);
                dst[k] = v ^ (((v >> shC) & 1u) << shT);
            }
            #pragma unroll
            for (int k = 0; k < VPT; k++)
                __stcs(&out4[dst[k]], a[k]);
        }
        // tail
        #pragma unroll
        for (int k = 0; k < VPT; k++) {
            unsigned int v = base + (unsigned int)k * BLK;
            if (v < nvec) {
                unsigned int dst = v ^ (((v >> shC) & 1u) << shT);
                __stcs(&out4[dst], __ldg(&x4[v]));
            }
        }
        return;
    }

    // Generic fallback: arbitrary d / batch (scalar, grid-stride).
    {
        unsigned long long Dn = 1;
        for (int k = 0; k < n; k++) Dn *= (unsigned)d;
        const unsigned int batch = (unsigned int)(total / Dn);
        unsigned long long pt = 1, pc = 1;
        for (int k = 0; k < n - 1 - target; k++)  pt *= (unsigned)d;
        for (int k = 0; k < n - 1 - control; k++) pc *= (unsigned)d;
        const float* x = (const float*)x4;
        float* out = (float*)out4;

        const unsigned int stride = blockDim.x * gridDim.x;
        for (unsigned int e = blockIdx.x * blockDim.x + threadIdx.x;
             e < total; e += stride) {
            unsigned long long i = e / batch;
            unsigned long long b = e - i * batch;
            long long dt  = (long long)((i / pt) % (unsigned)d);
            long long dcv = (long long)((i / pc) % (unsigned)d);
            long long lin = (long long)i + (((dt + dcv) % d) - dt) * (long long)pt;
            out[(unsigned long long)lin * batch + b] = x[e];
        }
    }
}

extern "C" void kernel_launch(void* const* d_in, const int* in_sizes, int n_in,
                              void* d_out, int out_size)
{
    const float* x       = (const float*)d_in[0];
    const int* p_control = (const int*)d_in[1];
    const int* p_target  = (const int*)d_in[2];
    const int* p_d       = (const int*)d_in[3];
    const int* p_n       = (const int*)d_in[4];
    float* out           = (float*)d_out;

    const unsigned int total = (unsigned int)in_sizes[0];
    const unsigned int nvec  = (total + 3u) >> 2;

    // Persistent grid; cap for tiny inputs.
    unsigned int needed = (nvec + (unsigned int)(BLK * VPT) - 1u)
                          / (unsigned int)(BLK * VPT);
    unsigned int grid = needed < GRID ? (needed ? needed : 1u) : GRID;

    cnot_kernel<<<grid, BLK>>>((const float4*)x, (float4*)out,
                               p_control, p_target, p_d, p_n,
                               nvec, total);
}

// round 6
// speedup vs baseline: 1.1273x; 1.1273x over previous
#include <cuda_runtime.h>
#include <cuda_bf16.h>
#include <cstdint>

// CNOT permutation: out[lin(i)*batch + b] = x[i*batch + b]
// d==2, pow2 batch>=4 fast path at float4 granularity:
//   v' = v XOR (bit(v, sc+lb-2) << (st+lb-2)),  lb = log2(batch)
// where sc = n-1-control, st = n-1-target. Exact because the scalar map is
// e' = e XOR (bit(e, sc+lb) << (st+lb)) and both shifted bit positions are >= 2.
//
// Session-certified roofline config (R3): flat grid, VPT=8, block=256,
// evict-first on both streams. All other tried variants (VPT=4, block=512,
// persistent grid-stride) were neutral or worse; kernel is HBM-bound at
// ~80% of spec (mixed read+write stream ceiling on HBM3e).

#define VPT 8  // float4 vectors per thread

__global__ __launch_bounds__(256) void cnot_kernel(
    const float4* __restrict__ x4, float4* __restrict__ out4,
    const int* __restrict__ p_control, const int* __restrict__ p_target,
    const int* __restrict__ p_d, const int* __restrict__ p_n,
    unsigned int nvec, unsigned int total)
{
    const int control = __ldg(p_control);
    const int target  = __ldg(p_target);
    const int d       = __ldg(p_d);
    const int n       = __ldg(p_n);

    bool fast = false;
    unsigned int shC = 0, shT = 0;
    if (d == 2 && n >= 1 && n < 32) {
        const unsigned int batch = total >> n;
        if ((batch << n) == total && batch >= 4u &&
            (batch & (batch - 1u)) == 0u) {
            const unsigned int lb = 31u - __clz(batch);
            shT = (unsigned int)(n - 1 - target) + lb - 2u;
            shC = (unsigned int)(n - 1 - control) + lb - 2u;
            fast = true;
        }
    }

    if (fast) {
        const unsigned int B = blockDim.x;
        unsigned int v0 = blockIdx.x * (B * VPT) + threadIdx.x;

        if (v0 + (VPT - 1) * B < nvec) {
            // full tile: batch all loads, then all stores (MLP = VPT)
            float4 a[VPT];
            unsigned int dst[VPT];
            #pragma unroll
            for (int k = 0; k < VPT; k++) {
                unsigned int v = v0 + (unsigned int)k * B;
                a[k]   = __ldcs(&x4[v]);                       // evict-first load
                dst[k] = v ^ (((v >> shC) & 1u) << shT);
            }
            #pragma unroll
            for (int k = 0; k < VPT; k++)
                __stcs(&out4[dst[k]], a[k]);                   // evict-first store
        } else {
            #pragma unroll
            for (int k = 0; k < VPT; k++) {
                unsigned int v = v0 + (unsigned int)k * B;
                if (v < nvec) {
                    unsigned int dst = v ^ (((v >> shC) & 1u) << shT);
                    __stcs(&out4[dst], __ldcs(&x4[v]));
                }
            }
        }
        return;
    }

    // Generic fallback: arbitrary d / batch (scalar).
    {
        unsigned long long Dn = 1;
        for (int k = 0; k < n; k++) Dn *= (unsigned)d;
        const unsigned int batch = (unsigned int)(total / Dn);
        unsigned long long pt = 1, pc = 1;
        for (int k = 0; k < n - 1 - target; k++)  pt *= (unsigned)d;
        for (int k = 0; k < n - 1 - control; k++) pc *= (unsigned)d;
        const float* x = (const float*)x4;
        float* out = (float*)out4;

        unsigned int e0 = (blockIdx.x * blockDim.x + threadIdx.x) * (4u * VPT);
        #pragma unroll
        for (int k = 0; k < 4 * VPT; k++) {
            unsigned int e = e0 + (unsigned)k;
            if (e >= total) break;
            unsigned long long i = e / batch;
            unsigned long long b = e - i * batch;
            long long dt  = (long long)((i / pt) % (unsigned)d);
            long long dcv = (long long)((i / pc) % (unsigned)d);
            long long lin = (long long)i + (((dt + dcv) % d) - dt) * (long long)pt;
            out[(unsigned long long)lin * batch + b] = x[e];
        }
    }
}

extern "C" void kernel_launch(void* const* d_in, const int* in_sizes, int n_in,
                              void* d_out, int out_size)
{
    const float* x       = (const float*)d_in[0];
    const int* p_control = (const int*)d_in[1];
    const int* p_target  = (const int*)d_in[2];
    const int* p_d       = (const int*)d_in[3];
    const int* p_n       = (const int*)d_in[4];
    float* out           = (float*)d_out;

    const unsigned int total = (unsigned int)in_sizes[0];
    const unsigned int nvec  = (total + 3u) >> 2;

    const int block = 256;
    const unsigned int grid =
        (nvec + (unsigned int)(block * VPT) - 1u) / (unsigned int)(block * VPT);

    cnot_kernel<<<grid, block>>>((const float4*)x, (float4*)out,
                                 p_control, p_target, p_d, p_n,
                                 nvec, total);
}